// round 16
// baseline (speedup 1.0000x reference)
#include <cuda_runtime.h>
#include <cuda_bf16.h>
#include <cuda_fp16.h>
#include <cstdint>

#define NB 2
#define NS 2048
#define NDM 512
#define NH 8
#define NDH 64
#define LOG2E 1.4426950408889634f

// ---------------------------------------------------------------------------
// Scratch (__device__ globals; no allocation allowed)
// ---------------------------------------------------------------------------
__device__ __half g_A16[3*4096*512];        // inputs (q,k,v), single fp16
__device__ __half g_Wt16[4*512*512];        // transposed weights [n][k], fp16
__device__ __half g_Qh16[NB*NH*NS*NDH];     // head-layout projections (fp16)
__device__ __half g_Kh16[NB*NH*NS*NDH];
__device__ __half g_Vh16[NB*NH*NS*NDH];
__device__ __half g_attn16[4096*512];       // attention output (merged heads), fp16
__device__ uint8_t g_mflag[NB*16*32];       // [b][qtile128][ktile64] mask-nonzero flag

// ---------------------------------------------------------------------------
// PTX helpers (baseline sm_80+ instructions only)
// ---------------------------------------------------------------------------
__device__ __forceinline__ uint32_t smem_u32(const void* p) {
    uint32_t a;
    asm("{ .reg .u64 t; cvta.to.shared.u64 t, %1; cvt.u32.u64 %0, t; }" : "=r"(a) : "l"(p));
    return a;
}
__device__ __forceinline__ void mma16816h(float* c, const uint32_t* a, const uint32_t* b) {
    asm volatile(
        "mma.sync.aligned.m16n8k16.row.col.f32.f16.f16.f32 "
        "{%0,%1,%2,%3}, {%4,%5,%6,%7}, {%8,%9}, {%0,%1,%2,%3};"
        : "+f"(c[0]), "+f"(c[1]), "+f"(c[2]), "+f"(c[3])
        : "r"(a[0]), "r"(a[1]), "r"(a[2]), "r"(a[3]), "r"(b[0]), "r"(b[1]));
}
__device__ __forceinline__ void ldsm_x4(uint32_t* r, uint32_t addr) {
    asm volatile("ldmatrix.sync.aligned.m8n8.x4.shared.b16 {%0,%1,%2,%3}, [%4];"
        : "=r"(r[0]), "=r"(r[1]), "=r"(r[2]), "=r"(r[3]) : "r"(addr));
}
__device__ __forceinline__ void ldsm_x4_t(uint32_t* r, uint32_t addr) {
    asm volatile("ldmatrix.sync.aligned.m8n8.x4.trans.shared.b16 {%0,%1,%2,%3}, [%4];"
        : "=r"(r[0]), "=r"(r[1]), "=r"(r[2]), "=r"(r[3]) : "r"(addr));
}
__device__ __forceinline__ void cpa16(uint32_t dst, const void* src) {
    asm volatile("cp.async.cg.shared.global [%0], [%1], 16;" :: "r"(dst), "l"(src));
}
#define CP_COMMIT() asm volatile("cp.async.commit_group;")
__device__ __forceinline__ uint32_t sw128(uint32_t off) {
    return off ^ ((off >> 3) & 0x70);
}
__device__ __forceinline__ float ex2f(float x) {
    float y; asm("ex2.approx.f32 %0, %1;" : "=f"(y) : "f"(x)); return y;
}
__device__ __forceinline__ uint32_t pack_h2(float a, float b) {
    __half2 t = __floats2half2_rn(a, b);
    return *reinterpret_cast<uint32_t*>(&t);
}

// ---------------------------------------------------------------------------
// Fused prep kernel: conv_in (blocks 0..6143) | conv_w (6144..7167) |
// mask_flag (7168..8191). Uniform per-block branch; all paths 256 threads.
// ---------------------------------------------------------------------------
__global__ void __launch_bounds__(256) prep_kernel(
    const float* __restrict__ q, const float* __restrict__ k, const float* __restrict__ v,
    const float* __restrict__ wq, const float* __restrict__ wk,
    const float* __restrict__ wv, const float* __restrict__ wo,
    const float* __restrict__ mask)
{
    __shared__ float t[32][33];
    const int bidx = blockIdx.x;
    const int tid  = threadIdx.x;

    if (bidx < 6144) {
        const int z = bidx >> 11;
        const int x = bidx & 2047;
        const float* src = (z == 0) ? q : (z == 1) ? k : v;
        const size_t idx = ((size_t)x * 256 + tid) * 4;
        float4 a = *reinterpret_cast<const float4*>(src + idx);
        const size_t o = (size_t)z * 4096 * 512 + idx;
        *reinterpret_cast<uint2*>(&g_A16[o]) =
            make_uint2(pack_h2(a.x, a.y), pack_h2(a.z, a.w));
    } else if (bidx < 7168) {
        const int wi = bidx - 6144;
        const int z  = wi >> 8;
        const int bx = wi & 15, by = (wi >> 4) & 15;
        const float* w = (z == 0) ? wq : (z == 1) ? wk : (z == 2) ? wv : wo;
        const int n0 = bx * 32, k0 = by * 32;
        const int tx = tid & 31, ty = tid >> 5;
        #pragma unroll
        for (int i = 0; i < 4; ++i)
            t[ty + 8*i][tx] = w[(size_t)(k0 + ty + 8*i) * 512 + n0 + tx];
        __syncthreads();
        #pragma unroll
        for (int i = 0; i < 4; ++i) {
            const int n = n0 + ty + 8*i, kk = k0 + tx;
            g_Wt16[(size_t)z * 262144 + (size_t)n * 512 + kk] =
                __float2half_rn(t[tx][ty + 8*i]);
        }
    } else {
        const int wi = bidx - 7168;
        const int kt = wi & 31, qt = (wi >> 5) & 15, b = wi >> 9;
        const int row = tid >> 1;
        const int c0  = (tid & 1) * 32;
        const float* mp = mask + ((size_t)b*NS + (size_t)qt*128 + row)*NS + (size_t)kt*64 + c0;
        const float4* rp = reinterpret_cast<const float4*>(mp);
        int nz = 0;
        #pragma unroll
        for (int i = 0; i < 8; ++i) {
            float4 vv = rp[i];
            nz |= (vv.x != 0.f) || (vv.y != 0.f) || (vv.z != 0.f) || (vv.w != 0.f);
        }
        nz = __syncthreads_or(nz);
        if (tid == 0) g_mflag[(b*16 + qt)*32 + kt] = (uint8_t)(nz ? 1 : 0);
    }
}

// ---------------------------------------------------------------------------
// GEMM: 64x128 CTA tile, 4 warps (2m x 2n), warp tile 32x64.
// K-chunk 64, 3-stage cp.async, no redundant bottom barrier.
// MODE 0: qkv — writes fp16 head layout (Q scaled log2e/8)
// MODE 1: out — writes fp32 flat + bias
// ---------------------------------------------------------------------------
#define GEMM_STAGE 24576u      // A 8K + W 16K
#define GEMM_SMEM  (3*GEMM_STAGE)

template<int MODE>
__global__ void __launch_bounds__(128) gemm_mma_kernel(
    const float* __restrict__ b0, const float* __restrict__ b1,
    const float* __restrict__ b2, float* __restrict__ outp)
{
    extern __shared__ char smem[];
    const uint32_t sb = smem_u32(smem);
    const int tid  = threadIdx.x;
    const int lane = tid & 31;
    const int warp = tid >> 5;
    const int wm   = warp & 1;
    const int wn   = warp >> 1;
    const int z    = (MODE == 0) ? blockIdx.z : 3;
    const int n0   = blockIdx.x * 128;
    const int m0   = blockIdx.y * 64;

    const char* Ap = (MODE == 0) ? (const char*)(g_A16 + (size_t)z*4096*512)
                                 : (const char*)g_attn16;
    const char* Wp = (const char*)(g_Wt16 + (size_t)z*262144);
    const float* bias = (MODE == 0) ? ((z == 0) ? b0 : (z == 1) ? b1 : b2) : b0;

    auto load_chunk = [&](int c, int st) {
        const uint32_t base = sb + (uint32_t)st * GEMM_STAGE;
        #pragma unroll
        for (int i = 0; i < 4; ++i) {
            const int e = tid + 128*i;
            const int row = e >> 3, seg = e & 7;
            const uint32_t sw = sw128((uint32_t)row*128u + seg*16u);
            cpa16(base + sw, Ap + (size_t)(m0 + row)*1024 + (size_t)c*128 + seg*16);
        }
        #pragma unroll
        for (int i = 0; i < 8; ++i) {
            const int e = tid + 128*i;
            const int row = e >> 3, seg = e & 7;
            const uint32_t sw = sw128((uint32_t)row*128u + seg*16u);
            cpa16(base + 8192 + sw, Wp + (size_t)(n0 + row)*1024 + (size_t)c*128 + seg*16);
        }
        CP_COMMIT();
    };

    float acc[2][8][4];
    #pragma unroll
    for (int m = 0; m < 2; ++m)
        #pragma unroll
        for (int bq = 0; bq < 8; ++bq)
            #pragma unroll
            for (int cI = 0; cI < 4; ++cI) acc[m][bq][cI] = 0.f;

    const int g  = lane >> 3, lr = lane & 7;
    const int arow = wm*32 + lr + ((g & 1) ? 8 : 0);
    const int acol = (g >= 2) ? 16 : 0;
    const int brow = lr + ((g >= 2) ? 8 : 0);
    const int bcol = (g & 1) ? 16 : 0;

    load_chunk(0, 0);
    load_chunk(1, 1);
    for (int c = 0; c < 8; ++c) {
        if (c < 7) { asm volatile("cp.async.wait_group 1;" ::: "memory"); }
        else       { asm volatile("cp.async.wait_group 0;" ::: "memory"); }
        __syncthreads();
        if (c + 2 < 8) load_chunk(c + 2, (c + 2) % 3);

        const uint32_t stb = sb + (uint32_t)(c % 3) * GEMM_STAGE;
        #pragma unroll
        for (int ks = 0; ks < 4; ++ks) {
            uint32_t a0[4], a1[4];
            ldsm_x4(a0, stb + sw128((uint32_t)arow*128u + 32*ks + acol));
            ldsm_x4(a1, stb + sw128((uint32_t)(arow + 16)*128u + 32*ks + acol));
            #pragma unroll
            for (int np = 0; np < 4; ++np) {
                const uint32_t sw = sw128((uint32_t)(wn*64 + np*16 + brow)*128u + 32*ks + bcol);
                uint32_t w4[4];
                ldsm_x4(w4, stb + 8192 + sw);
                mma16816h(acc[0][2*np],   a0, w4);
                mma16816h(acc[0][2*np+1], a0, w4+2);
                mma16816h(acc[1][2*np],   a1, w4);
                mma16816h(acc[1][2*np+1], a1, w4+2);
            }
        }
    }

    // epilogue
    const int r  = lane >> 2;
    const int tq = lane & 3;
    const float sc = (MODE == 0 && z == 0) ? 0.125f * LOG2E : 1.f;
    __half* outh = (z == 0) ? g_Qh16 : (z == 1) ? g_Kh16 : g_Vh16;
    #pragma unroll
    for (int mt = 0; mt < 2; ++mt) {
        #pragma unroll
        for (int np = 0; np < 4; ++np) {
            #pragma unroll
            for (int sub = 0; sub < 2; ++sub) {
                const float* c4 = acc[mt][2*np + sub];
                const int row0 = m0 + wm*32 + mt*16 + r;
                const int col  = n0 + wn*64 + np*16 + sub*8 + 2*tq;
                const float bv0 = bias[col], bv1 = bias[col + 1];
                if (MODE == 1) {
                    *reinterpret_cast<float2*>(outp + (size_t)row0*512 + col) =
                        make_float2(c4[0] + bv0, c4[1] + bv1);
                    *reinterpret_cast<float2*>(outp + (size_t)(row0+8)*512 + col) =
                        make_float2(c4[2] + bv0, c4[3] + bv1);
                } else {
                    #pragma unroll
                    for (int rr = 0; rr < 2; ++rr) {
                        const int row = row0 + rr*8;
                        const int bb = row >> 11, s = row & 2047;
                        const int hh = col >> 6,  d = col & 63;
                        const size_t o = (((size_t)bb*NH + hh)*NS + s)*NDH + d;
                        *reinterpret_cast<uint32_t*>(&outh[o]) =
                            pack_h2((c4[2*rr] + bv0)*sc, (c4[2*rr+1] + bv1)*sc);
                    }
                }
            }
        }
    }
}

// ---------------------------------------------------------------------------
// Flash attention (HMMA fp16), wide-M warps, ones-MMA row sums, log2-domain Q.
// k-tile = 128 (16 iterations, half the barriers), 3-stage cp.async pipeline
// (Q 16KB + 3x32KB = 112KB, 2 CTAs/SM). Mask-flag skip on all-zero tiles.
// Bit-identical math to round 14.
// ---------------------------------------------------------------------------
#define A_Q      0
#define A_KV     16384
#define KV_STAGE 32768          // Kh 16K | Vh 16K
#define ATT_SMEM (A_KV + 3*KV_STAGE)   // 114688

__global__ void __launch_bounds__(128) attn_mma_kernel(const float* __restrict__ mask)
{
    extern __shared__ char smem[];
    const uint32_t sb = smem_u32(smem);
    const int tid  = threadIdx.x;
    const int lane = tid & 31;
    const int qg   = tid >> 5;
    const int bh   = blockIdx.y;
    const int b    = bh >> 3;
    const int h    = bh & 7;
    const int q0   = blockIdx.x * 128;

    const int g  = lane >> 3, lr = lane & 7;
    const int r  = lane >> 2, tq = lane & 3;

    const char* Khp = (const char*)(g_Kh16 + (size_t)bh*NS*NDH);
    const char* Vhp = (const char*)(g_Vh16 + (size_t)bh*NS*NDH);

    // load one 128-key tile (K and V, 16KB each) into stage slot
    auto load_kv = [&](int t, int slot) {
        const uint32_t base = sb + A_KV + (uint32_t)slot*KV_STAGE;
        const size_t goff = (size_t)t * 128 * 128;   // 128 rows x 128B
        #pragma unroll
        for (int i = 0; i < 8; ++i) {
            const int e = tid + 128*i;               // 1024 (row,seg) pairs
            const int row = e >> 3, seg = e & 7;
            const uint32_t sw = sw128((uint32_t)row*128u + seg*16u);
            const size_t off = goff + (size_t)row*128 + seg*16;
            cpa16(base + sw,          Khp + off);
            cpa16(base + 16384 + sw,  Vhp + off);
        }
        CP_COMMIT();
    };

    load_kv(0, 0);
    load_kv(1, 1);

    uint32_t fw[8];
    {
        const uint4* fp = reinterpret_cast<const uint4*>(g_mflag + (b*16 + blockIdx.x)*32);
        uint4 f0 = fp[0], f1 = fp[1];
        fw[0]=f0.x; fw[1]=f0.y; fw[2]=f0.z; fw[3]=f0.w;
        fw[4]=f1.x; fw[5]=f1.y; fw[6]=f1.z; fw[7]=f1.w;
    }

    {
        const char* Qp = (const char*)(g_Qh16 + (size_t)(bh*NS + q0)*NDH);
        #pragma unroll
        for (int i = 0; i < 8; ++i) {
            const int e = tid + 128*i;
            const uint32_t off = (uint32_t)(e >> 3)*128u + (uint32_t)(e & 7)*16u;
            *reinterpret_cast<uint4*>(smem + A_Q + sw128(off)) =
                *reinterpret_cast<const uint4*>(Qp + off);
        }
    }
    __syncthreads();

    const int qrow0 = qg*32 + lr + ((g & 1) ? 8 : 0);
    const int qcol  = (g >= 2) ? 16 : 0;
    uint32_t qf0[4][4], qf1[4][4];
    #pragma unroll
    for (int ks = 0; ks < 4; ++ks) {
        ldsm_x4(qf0[ks], sb + A_Q + sw128((uint32_t)qrow0*128u + 32*ks + qcol));
        ldsm_x4(qf1[ks], sb + A_Q + sw128((uint32_t)(qrow0 + 16)*128u + 32*ks + qcol));
    }

    const int krow = lr + ((g >= 2) ? 8 : 0);
    const int kcol = (g & 1) ? 16 : 0;
    const int vrow = lr + ((g & 1) ? 8 : 0);
    const int vcol = (g >= 2) ? 16 : 0;

    float oacc[2][8][4];
    #pragma unroll
    for (int m = 0; m < 2; ++m)
        #pragma unroll
        for (int j = 0; j < 8; ++j)
            #pragma unroll
            for (int cI = 0; cI < 4; ++cI) oacc[m][j][cI] = 0.f;
    float la0[4] = {0.f, 0.f, 0.f, 0.f};
    float la1[4] = {0.f, 0.f, 0.f, 0.f};
    const uint32_t ones2[2] = {0x3C003C00u, 0x3C003C00u};

    const float MC = -1e9f * LOG2E;
    const float* mr = mask + ((size_t)b*NS + (q0 + qg*32 + r))*NS + 2*tq;

    for (int t = 0; t < NS/128; ++t) {
        const int kt = t * 128;
        if (t < 15) { asm volatile("cp.async.wait_group 1;" ::: "memory"); }
        else        { asm volatile("cp.async.wait_group 0;" ::: "memory"); }
        __syncthreads();
        if (t + 2 < NS/128) load_kv(t + 2, (t + 2) % 3);

        const uint32_t stb = sb + A_KV + (uint32_t)(t % 3)*KV_STAGE;
        const bool tile_masked =
            ((fw[t >> 1] >> ((t & 1) * 16)) & 0xFFFFu) != 0u;

        #pragma unroll 4
        for (int nc = 0; nc < 8; ++nc) {
            float s0A[4] = {0,0,0,0}, s0B[4] = {0,0,0,0};
            float s1A[4] = {0,0,0,0}, s1B[4] = {0,0,0,0};
            #pragma unroll
            for (int ks = 0; ks < 4; ++ks) {
                uint32_t k4[4];
                ldsm_x4(k4, stb + sw128((uint32_t)(16*nc + krow)*128u + 32*ks + kcol));
                mma16816h(s0A, qf0[ks], k4); mma16816h(s0B, qf0[ks], k4+2);
                mma16816h(s1A, qf1[ks], k4); mma16816h(s1B, qf1[ks], k4+2);
            }

            uint32_t pa0[4], pa1[4];
            if (tile_masked) {
                #pragma unroll
                for (int m = 0; m < 2; ++m) {
                    const float* sA = (m == 0) ? s0A : s1A;
                    const float* sB = (m == 0) ? s0B : s1B;
                    uint32_t* pa = (m == 0) ? pa0 : pa1;
                    const float* mra = mr + (size_t)(m*16)*NS;
                    #pragma unroll
                    for (int jj = 0; jj < 2; ++jj) {
                        const float* s4 = (jj == 0) ? sA : sB;
                        const size_t ko = (size_t)(kt + nc*16 + 8*jj);
                        const float2 f0 = *reinterpret_cast<const float2*>(mra + ko);
                        const float2 f1 = *reinterpret_cast<const float2*>(mra + (size_t)8*NS + ko);
                        const float p00 = ex2f(fmaf(f0.x, MC, s4[0]));
                        const float p01 = ex2f(fmaf(f0.y, MC, s4[1]));
                        const float p10 = ex2f(fmaf(f1.x, MC, s4[2]));
                        const float p11 = ex2f(fmaf(f1.y, MC, s4[3]));
                        pa[2*jj]     = pack_h2(p00, p01);
                        pa[2*jj + 1] = pack_h2(p10, p11);
                    }
                }
            } else {
                #pragma unroll
                for (int m = 0; m < 2; ++m) {
                    const float* sA = (m == 0) ? s0A : s1A;
                    const float* sB = (m == 0) ? s0B : s1B;
                    uint32_t* pa = (m == 0) ? pa0 : pa1;
                    #pragma unroll
                    for (int jj = 0; jj < 2; ++jj) {
                        const float* s4 = (jj == 0) ? sA : sB;
                        const float p00 = ex2f(s4[0]);
                        const float p01 = ex2f(s4[1]);
                        const float p10 = ex2f(s4[2]);
                        const float p11 = ex2f(s4[3]);
                        pa[2*jj]     = pack_h2(p00, p01);
                        pa[2*jj + 1] = pack_h2(p10, p11);
                    }
                }
            }

            mma16816h(la0, pa0, ones2);
            mma16816h(la1, pa1, ones2);

            #pragma unroll
            for (int nd = 0; nd < 4; ++nd) {
                uint32_t v4[4];
                ldsm_x4_t(v4, stb + 16384 + sw128((uint32_t)(16*nc + vrow)*128u + 32*nd + vcol));
                mma16816h(oacc[0][2*nd],   pa0, v4);
                mma16816h(oacc[0][2*nd+1], pa0, v4+2);
                mma16816h(oacc[1][2*nd],   pa1, v4);
                mma16816h(oacc[1][2*nd+1], pa1, v4+2);
            }
        }
    }

    const float inv[4] = {1.f/la0[0], 1.f/la0[2], 1.f/la1[0], 1.f/la1[2]};

    #pragma unroll
    for (int m = 0; m < 2; ++m) {
        const int row0 = b*NS + q0 + qg*32 + m*16 + r;
        #pragma unroll
        for (int j = 0; j < 8; ++j) {
            const int col = h*NDH + 8*j + 2*tq;
            *reinterpret_cast<uint32_t*>(&g_attn16[(size_t)row0*512 + col]) =
                pack_h2(oacc[m][j][0]*inv[2*m], oacc[m][j][1]*inv[2*m]);
            *reinterpret_cast<uint32_t*>(&g_attn16[(size_t)(row0+8)*512 + col]) =
                pack_h2(oacc[m][j][2]*inv[2*m+1], oacc[m][j][3]*inv[2*m+1]);
        }
    }
}

// ---------------------------------------------------------------------------
extern "C" void kernel_launch(void* const* d_in, const int* in_sizes, int n_in,
                              void* d_out, int out_size)
{
    const float* query = (const float*)d_in[0];
    const float* key   = (const float*)d_in[1];
    const float* value = (const float*)d_in[2];
    const float* mask  = (const float*)d_in[3];
    const float* wq    = (const float*)d_in[4];
    const float* bq    = (const float*)d_in[5];
    const float* wk    = (const float*)d_in[6];
    const float* bk    = (const float*)d_in[7];
    const float* wv    = (const float*)d_in[8];
    const float* bv    = (const float*)d_in[9];
    const float* wo    = (const float*)d_in[10];
    const float* bo    = (const float*)d_in[11];
    float* out = (float*)d_out;

    cudaFuncSetAttribute(gemm_mma_kernel<0>, cudaFuncAttributeMaxDynamicSharedMemorySize, GEMM_SMEM);
    cudaFuncSetAttribute(gemm_mma_kernel<1>, cudaFuncAttributeMaxDynamicSharedMemorySize, GEMM_SMEM);
    cudaFuncSetAttribute(attn_mma_kernel,    cudaFuncAttributeMaxDynamicSharedMemorySize, ATT_SMEM);

    prep_kernel<<<8192, 256>>>(query, key, value, wq, wk, wv, wo, mask);

    dim3 gq(NDM/128, 4096/64, 3);           // (4, 64, 3)
    gemm_mma_kernel<0><<<gq, 128, GEMM_SMEM>>>(bq, bk, bv, nullptr);

    dim3 ga(NS/128, NB*NH);                 // (16, 16)
    attn_mma_kernel<<<ga, 128, ATT_SMEM>>>(mask);

    dim3 go(NDM/128, 4096/64);              // (4, 64)
    gemm_mma_kernel<1><<<go, 128, GEMM_SMEM>>>(bo, nullptr, nullptr, out);
}

// round 17
// speedup vs baseline: 1.0625x; 1.0625x over previous
#include <cuda_runtime.h>
#include <cuda_bf16.h>
#include <cuda_fp16.h>
#include <cstdint>

#define NB 2
#define NS 2048
#define NDM 512
#define NH 8
#define NDH 64
#define LOG2E 1.4426950408889634f

// ---------------------------------------------------------------------------
// Scratch (__device__ globals; no allocation allowed)
// ---------------------------------------------------------------------------
__device__ __half g_A16[3*4096*512];        // inputs (q,k,v), single fp16
__device__ __half g_Wt16[4*512*512];        // transposed weights [n][k], fp16
__device__ __half g_Qh16[NB*NH*NS*NDH];     // head-layout projections (fp16)
__device__ __half g_Kh16[NB*NH*NS*NDH];
__device__ __half g_Vh16[NB*NH*NS*NDH];
__device__ __half g_attn16[4096*512];       // attention output (merged heads), fp16
__device__ uint8_t g_mflag[NB*16*32];       // [b][qtile128][ktile64] mask-nonzero flag

// ---------------------------------------------------------------------------
// PTX helpers (baseline sm_80+ instructions only)
// ---------------------------------------------------------------------------
__device__ __forceinline__ uint32_t smem_u32(const void* p) {
    uint32_t a;
    asm("{ .reg .u64 t; cvta.to.shared.u64 t, %1; cvt.u32.u64 %0, t; }" : "=r"(a) : "l"(p));
    return a;
}
__device__ __forceinline__ void mma16816h(float* c, const uint32_t* a, const uint32_t* b) {
    asm volatile(
        "mma.sync.aligned.m16n8k16.row.col.f32.f16.f16.f32 "
        "{%0,%1,%2,%3}, {%4,%5,%6,%7}, {%8,%9}, {%0,%1,%2,%3};"
        : "+f"(c[0]), "+f"(c[1]), "+f"(c[2]), "+f"(c[3])
        : "r"(a[0]), "r"(a[1]), "r"(a[2]), "r"(a[3]), "r"(b[0]), "r"(b[1]));
}
__device__ __forceinline__ void ldsm_x4(uint32_t* r, uint32_t addr) {
    asm volatile("ldmatrix.sync.aligned.m8n8.x4.shared.b16 {%0,%1,%2,%3}, [%4];"
        : "=r"(r[0]), "=r"(r[1]), "=r"(r[2]), "=r"(r[3]) : "r"(addr));
}
__device__ __forceinline__ void ldsm_x4_t(uint32_t* r, uint32_t addr) {
    asm volatile("ldmatrix.sync.aligned.m8n8.x4.trans.shared.b16 {%0,%1,%2,%3}, [%4];"
        : "=r"(r[0]), "=r"(r[1]), "=r"(r[2]), "=r"(r[3]) : "r"(addr));
}
__device__ __forceinline__ void cpa16(uint32_t dst, const void* src) {
    asm volatile("cp.async.cg.shared.global [%0], [%1], 16;" :: "r"(dst), "l"(src));
}
#define CP_COMMIT() asm volatile("cp.async.commit_group;")
__device__ __forceinline__ uint32_t sw128(uint32_t off) {
    return off ^ ((off >> 3) & 0x70);
}
__device__ __forceinline__ float ex2f(float x) {
    float y; asm("ex2.approx.f32 %0, %1;" : "=f"(y) : "f"(x)); return y;
}
__device__ __forceinline__ uint32_t pack_h2(float a, float b) {
    __half2 t = __floats2half2_rn(a, b);
    return *reinterpret_cast<uint32_t*>(&t);
}

// ---------------------------------------------------------------------------
// Fused prep kernel: conv_in (blocks 0..6143) | conv_w (6144..7167) |
// mask_flag (7168..8191). Uniform per-block branch; all paths 256 threads.
// ---------------------------------------------------------------------------
__global__ void __launch_bounds__(256) prep_kernel(
    const float* __restrict__ q, const float* __restrict__ k, const float* __restrict__ v,
    const float* __restrict__ wq, const float* __restrict__ wk,
    const float* __restrict__ wv, const float* __restrict__ wo,
    const float* __restrict__ mask)
{
    __shared__ float t[32][33];
    const int bidx = blockIdx.x;
    const int tid  = threadIdx.x;

    if (bidx < 6144) {
        const int z = bidx >> 11;
        const int x = bidx & 2047;
        const float* src = (z == 0) ? q : (z == 1) ? k : v;
        const size_t idx = ((size_t)x * 256 + tid) * 4;
        float4 a = *reinterpret_cast<const float4*>(src + idx);
        const size_t o = (size_t)z * 4096 * 512 + idx;
        *reinterpret_cast<uint2*>(&g_A16[o]) =
            make_uint2(pack_h2(a.x, a.y), pack_h2(a.z, a.w));
    } else if (bidx < 7168) {
        const int wi = bidx - 6144;
        const int z  = wi >> 8;
        const int bx = wi & 15, by = (wi >> 4) & 15;
        const float* w = (z == 0) ? wq : (z == 1) ? wk : (z == 2) ? wv : wo;
        const int n0 = bx * 32, k0 = by * 32;
        const int tx = tid & 31, ty = tid >> 5;
        #pragma unroll
        for (int i = 0; i < 4; ++i)
            t[ty + 8*i][tx] = w[(size_t)(k0 + ty + 8*i) * 512 + n0 + tx];
        __syncthreads();
        #pragma unroll
        for (int i = 0; i < 4; ++i) {
            const int n = n0 + ty + 8*i, kk = k0 + tx;
            g_Wt16[(size_t)z * 262144 + (size_t)n * 512 + kk] =
                __float2half_rn(t[tx][ty + 8*i]);
        }
    } else {
        const int wi = bidx - 7168;
        const int kt = wi & 31, qt = (wi >> 5) & 15, b = wi >> 9;
        const int row = tid >> 1;
        const int c0  = (tid & 1) * 32;
        const float* mp = mask + ((size_t)b*NS + (size_t)qt*128 + row)*NS + (size_t)kt*64 + c0;
        const float4* rp = reinterpret_cast<const float4*>(mp);
        int nz = 0;
        #pragma unroll
        for (int i = 0; i < 8; ++i) {
            float4 vv = rp[i];
            nz |= (vv.x != 0.f) || (vv.y != 0.f) || (vv.z != 0.f) || (vv.w != 0.f);
        }
        nz = __syncthreads_or(nz);
        if (tid == 0) g_mflag[(b*16 + qt)*32 + kt] = (uint8_t)(nz ? 1 : 0);
    }
}

// ---------------------------------------------------------------------------
// GEMM: 64x128 CTA tile, 4 warps (2m x 2n), warp tile 32x64.
// K-chunk 64, 3-stage cp.async, 3 CTAs/SM (regs capped at 170 >= current 166).
// MODE 0: qkv — writes fp16 head layout (Q scaled log2e/8)
// MODE 1: out — writes fp32 flat + bias
// ---------------------------------------------------------------------------
#define GEMM_STAGE 24576u      // A 8K + W 16K
#define GEMM_SMEM  (3*GEMM_STAGE)

template<int MODE>
__global__ void __launch_bounds__(128, 3) gemm_mma_kernel(
    const float* __restrict__ b0, const float* __restrict__ b1,
    const float* __restrict__ b2, float* __restrict__ outp)
{
    extern __shared__ char smem[];
    const uint32_t sb = smem_u32(smem);
    const int tid  = threadIdx.x;
    const int lane = tid & 31;
    const int warp = tid >> 5;
    const int wm   = warp & 1;
    const int wn   = warp >> 1;
    const int z    = (MODE == 0) ? blockIdx.z : 3;
    const int n0   = blockIdx.x * 128;
    const int m0   = blockIdx.y * 64;

    const char* Ap = (MODE == 0) ? (const char*)(g_A16 + (size_t)z*4096*512)
                                 : (const char*)g_attn16;
    const char* Wp = (const char*)(g_Wt16 + (size_t)z*262144);
    const float* bias = (MODE == 0) ? ((z == 0) ? b0 : (z == 1) ? b1 : b2) : b0;

    auto load_chunk = [&](int c, int st) {
        const uint32_t base = sb + (uint32_t)st * GEMM_STAGE;
        #pragma unroll
        for (int i = 0; i < 4; ++i) {
            const int e = tid + 128*i;
            const int row = e >> 3, seg = e & 7;
            const uint32_t sw = sw128((uint32_t)row*128u + seg*16u);
            cpa16(base + sw, Ap + (size_t)(m0 + row)*1024 + (size_t)c*128 + seg*16);
        }
        #pragma unroll
        for (int i = 0; i < 8; ++i) {
            const int e = tid + 128*i;
            const int row = e >> 3, seg = e & 7;
            const uint32_t sw = sw128((uint32_t)row*128u + seg*16u);
            cpa16(base + 8192 + sw, Wp + (size_t)(n0 + row)*1024 + (size_t)c*128 + seg*16);
        }
        CP_COMMIT();
    };

    float acc[2][8][4];
    #pragma unroll
    for (int m = 0; m < 2; ++m)
        #pragma unroll
        for (int bq = 0; bq < 8; ++bq)
            #pragma unroll
            for (int cI = 0; cI < 4; ++cI) acc[m][bq][cI] = 0.f;

    const int g  = lane >> 3, lr = lane & 7;
    const int arow = wm*32 + lr + ((g & 1) ? 8 : 0);
    const int acol = (g >= 2) ? 16 : 0;
    const int brow = lr + ((g >= 2) ? 8 : 0);
    const int bcol = (g & 1) ? 16 : 0;

    load_chunk(0, 0);
    load_chunk(1, 1);
    for (int c = 0; c < 8; ++c) {
        if (c < 7) { asm volatile("cp.async.wait_group 1;" ::: "memory"); }
        else       { asm volatile("cp.async.wait_group 0;" ::: "memory"); }
        __syncthreads();
        if (c + 2 < 8) load_chunk(c + 2, (c + 2) % 3);

        const uint32_t stb = sb + (uint32_t)(c % 3) * GEMM_STAGE;
        #pragma unroll
        for (int ks = 0; ks < 4; ++ks) {
            uint32_t a0[4], a1[4];
            ldsm_x4(a0, stb + sw128((uint32_t)arow*128u + 32*ks + acol));
            ldsm_x4(a1, stb + sw128((uint32_t)(arow + 16)*128u + 32*ks + acol));
            #pragma unroll
            for (int np = 0; np < 4; ++np) {
                const uint32_t sw = sw128((uint32_t)(wn*64 + np*16 + brow)*128u + 32*ks + bcol);
                uint32_t w4[4];
                ldsm_x4(w4, stb + 8192 + sw);
                mma16816h(acc[0][2*np],   a0, w4);
                mma16816h(acc[0][2*np+1], a0, w4+2);
                mma16816h(acc[1][2*np],   a1, w4);
                mma16816h(acc[1][2*np+1], a1, w4+2);
            }
        }
    }

    // epilogue
    const int r  = lane >> 2;
    const int tq = lane & 3;
    const float sc = (MODE == 0 && z == 0) ? 0.125f * LOG2E : 1.f;
    __half* outh = (z == 0) ? g_Qh16 : (z == 1) ? g_Kh16 : g_Vh16;
    #pragma unroll
    for (int mt = 0; mt < 2; ++mt) {
        #pragma unroll
        for (int np = 0; np < 4; ++np) {
            #pragma unroll
            for (int sub = 0; sub < 2; ++sub) {
                const float* c4 = acc[mt][2*np + sub];
                const int row0 = m0 + wm*32 + mt*16 + r;
                const int col  = n0 + wn*64 + np*16 + sub*8 + 2*tq;
                const float bv0 = bias[col], bv1 = bias[col + 1];
                if (MODE == 1) {
                    *reinterpret_cast<float2*>(outp + (size_t)row0*512 + col) =
                        make_float2(c4[0] + bv0, c4[1] + bv1);
                    *reinterpret_cast<float2*>(outp + (size_t)(row0+8)*512 + col) =
                        make_float2(c4[2] + bv0, c4[3] + bv1);
                } else {
                    #pragma unroll
                    for (int rr = 0; rr < 2; ++rr) {
                        const int row = row0 + rr*8;
                        const int bb = row >> 11, s = row & 2047;
                        const int hh = col >> 6,  d = col & 63;
                        const size_t o = (((size_t)bb*NH + hh)*NS + s)*NDH + d;
                        *reinterpret_cast<uint32_t*>(&outh[o]) =
                            pack_h2((c4[2*rr] + bv0)*sc, (c4[2*rr+1] + bv1)*sc);
                    }
                }
            }
        }
    }
}

// ---------------------------------------------------------------------------
// Flash attention (HMMA fp16) — round-14 champion configuration, unchanged:
// wide-M warps, ones-MMA row sums, log2-domain Q, 64-key tiles, 4-stage
// cp.async KV pipeline, mask-flag skip on all-zero tiles, no reg cap.
// ---------------------------------------------------------------------------
#define A_Q      0
#define A_KV     16384
#define KV_STAGE 16384          // Kh 8K | Vh 8K
#define ATT_SMEM (A_KV + 4*KV_STAGE)   // 81920

__global__ void __launch_bounds__(128) attn_mma_kernel(const float* __restrict__ mask)
{
    extern __shared__ char smem[];
    const uint32_t sb = smem_u32(smem);
    const int tid  = threadIdx.x;
    const int lane = tid & 31;
    const int qg   = tid >> 5;
    const int bh   = blockIdx.y;
    const int b    = bh >> 3;
    const int h    = bh & 7;
    const int q0   = blockIdx.x * 128;

    const int g  = lane >> 3, lr = lane & 7;
    const int r  = lane >> 2, tq = lane & 3;

    const char* Khp = (const char*)(g_Kh16 + (size_t)bh*NS*NDH);
    const char* Vhp = (const char*)(g_Vh16 + (size_t)bh*NS*NDH);

    auto load_kv = [&](int t, int slot) {
        const uint32_t base = sb + A_KV + (uint32_t)slot*KV_STAGE;
        const size_t goff = (size_t)t * 64 * 128;
        #pragma unroll
        for (int i = 0; i < 4; ++i) {
            const int e = tid + 128*i;
            const int row = e >> 3, seg = e & 7;
            const uint32_t sw = sw128((uint32_t)row*128u + seg*16u);
            const size_t off = goff + (size_t)row*128 + seg*16;
            cpa16(base + sw,         Khp + off);
            cpa16(base + 8192 + sw,  Vhp + off);
        }
        CP_COMMIT();
    };

    load_kv(0, 0);
    load_kv(1, 1);
    load_kv(2, 2);

    uint32_t fw[8];
    {
        const uint4* fp = reinterpret_cast<const uint4*>(g_mflag + (b*16 + blockIdx.x)*32);
        uint4 f0 = fp[0], f1 = fp[1];
        fw[0]=f0.x; fw[1]=f0.y; fw[2]=f0.z; fw[3]=f0.w;
        fw[4]=f1.x; fw[5]=f1.y; fw[6]=f1.z; fw[7]=f1.w;
    }

    {
        const char* Qp = (const char*)(g_Qh16 + (size_t)(bh*NS + q0)*NDH);
        #pragma unroll
        for (int i = 0; i < 8; ++i) {
            const int e = tid + 128*i;
            const uint32_t off = (uint32_t)(e >> 3)*128u + (uint32_t)(e & 7)*16u;
            *reinterpret_cast<uint4*>(smem + A_Q + sw128(off)) =
                *reinterpret_cast<const uint4*>(Qp + off);
        }
    }
    __syncthreads();

    const int qrow0 = qg*32 + lr + ((g & 1) ? 8 : 0);
    const int qcol  = (g >= 2) ? 16 : 0;
    uint32_t qf0[4][4], qf1[4][4];
    #pragma unroll
    for (int ks = 0; ks < 4; ++ks) {
        ldsm_x4(qf0[ks], sb + A_Q + sw128((uint32_t)qrow0*128u + 32*ks + qcol));
        ldsm_x4(qf1[ks], sb + A_Q + sw128((uint32_t)(qrow0 + 16)*128u + 32*ks + qcol));
    }

    const int krow = lr + ((g >= 2) ? 8 : 0);
    const int kcol = (g & 1) ? 16 : 0;
    const int vrow = lr + ((g & 1) ? 8 : 0);
    const int vcol = (g >= 2) ? 16 : 0;

    float oacc[2][8][4];
    #pragma unroll
    for (int m = 0; m < 2; ++m)
        #pragma unroll
        for (int j = 0; j < 8; ++j)
            #pragma unroll
            for (int cI = 0; cI < 4; ++cI) oacc[m][j][cI] = 0.f;
    float la0[4] = {0.f, 0.f, 0.f, 0.f};
    float la1[4] = {0.f, 0.f, 0.f, 0.f};
    const uint32_t ones2[2] = {0x3C003C00u, 0x3C003C00u};

    const float MC = -1e9f * LOG2E;
    const float* mr = mask + ((size_t)b*NS + (q0 + qg*32 + r))*NS + 2*tq;

    for (int t = 0; t < NS/64; ++t) {
        const int kt = t * 64;
        if (t < 30)      { asm volatile("cp.async.wait_group 2;" ::: "memory"); }
        else if (t == 30){ asm volatile("cp.async.wait_group 1;" ::: "memory"); }
        else             { asm volatile("cp.async.wait_group 0;" ::: "memory"); }
        __syncthreads();
        if (t + 3 < NS/64) load_kv(t + 3, (t + 3) & 3);

        const uint32_t stb = sb + A_KV + (uint32_t)(t & 3)*KV_STAGE;
        const bool tile_masked = ((fw[t >> 2] >> ((t & 3) * 8)) & 0xFFu) != 0u;

        #pragma unroll
        for (int nc = 0; nc < 4; ++nc) {
            float s0A[4] = {0,0,0,0}, s0B[4] = {0,0,0,0};
            float s1A[4] = {0,0,0,0}, s1B[4] = {0,0,0,0};
            #pragma unroll
            for (int ks = 0; ks < 4; ++ks) {
                uint32_t k4[4];
                ldsm_x4(k4, stb + sw128((uint32_t)(16*nc + krow)*128u + 32*ks + kcol));
                mma16816h(s0A, qf0[ks], k4); mma16816h(s0B, qf0[ks], k4+2);
                mma16816h(s1A, qf1[ks], k4); mma16816h(s1B, qf1[ks], k4+2);
            }

            uint32_t pa0[4], pa1[4];
            if (tile_masked) {
                #pragma unroll
                for (int m = 0; m < 2; ++m) {
                    const float* sA = (m == 0) ? s0A : s1A;
                    const float* sB = (m == 0) ? s0B : s1B;
                    uint32_t* pa = (m == 0) ? pa0 : pa1;
                    const float* mra = mr + (size_t)(m*16)*NS;
                    #pragma unroll
                    for (int jj = 0; jj < 2; ++jj) {
                        const float* s4 = (jj == 0) ? sA : sB;
                        const size_t ko = (size_t)(kt + nc*16 + 8*jj);
                        const float2 f0 = *reinterpret_cast<const float2*>(mra + ko);
                        const float2 f1 = *reinterpret_cast<const float2*>(mra + (size_t)8*NS + ko);
                        const float p00 = ex2f(fmaf(f0.x, MC, s4[0]));
                        const float p01 = ex2f(fmaf(f0.y, MC, s4[1]));
                        const float p10 = ex2f(fmaf(f1.x, MC, s4[2]));
                        const float p11 = ex2f(fmaf(f1.y, MC, s4[3]));
                        pa[2*jj]     = pack_h2(p00, p01);
                        pa[2*jj + 1] = pack_h2(p10, p11);
                    }
                }
            } else {
                #pragma unroll
                for (int m = 0; m < 2; ++m) {
                    const float* sA = (m == 0) ? s0A : s1A;
                    const float* sB = (m == 0) ? s0B : s1B;
                    uint32_t* pa = (m == 0) ? pa0 : pa1;
                    #pragma unroll
                    for (int jj = 0; jj < 2; ++jj) {
                        const float* s4 = (jj == 0) ? sA : sB;
                        const float p00 = ex2f(s4[0]);
                        const float p01 = ex2f(s4[1]);
                        const float p10 = ex2f(s4[2]);
                        const float p11 = ex2f(s4[3]);
                        pa[2*jj]     = pack_h2(p00, p01);
                        pa[2*jj + 1] = pack_h2(p10, p11);
                    }
                }
            }

            mma16816h(la0, pa0, ones2);
            mma16816h(la1, pa1, ones2);

            #pragma unroll
            for (int nd = 0; nd < 4; ++nd) {
                uint32_t v4[4];
                ldsm_x4_t(v4, stb + 8192 + sw128((uint32_t)(16*nc + vrow)*128u + 32*nd + vcol));
                mma16816h(oacc[0][2*nd],   pa0, v4);
                mma16816h(oacc[0][2*nd+1], pa0, v4+2);
                mma16816h(oacc[1][2*nd],   pa1, v4);
                mma16816h(oacc[1][2*nd+1], pa1, v4+2);
            }
        }
    }

    const float inv[4] = {1.f/la0[0], 1.f/la0[2], 1.f/la1[0], 1.f/la1[2]};

    #pragma unroll
    for (int m = 0; m < 2; ++m) {
        const int row0 = b*NS + q0 + qg*32 + m*16 + r;
        #pragma unroll
        for (int j = 0; j < 8; ++j) {
            const int col = h*NDH + 8*j + 2*tq;
            *reinterpret_cast<uint32_t*>(&g_attn16[(size_t)row0*512 + col]) =
                pack_h2(oacc[m][j][0]*inv[2*m], oacc[m][j][1]*inv[2*m]);
            *reinterpret_cast<uint32_t*>(&g_attn16[(size_t)(row0+8)*512 + col]) =
                pack_h2(oacc[m][j][2]*inv[2*m+1], oacc[m][j][3]*inv[2*m+1]);
        }
    }
}

// ---------------------------------------------------------------------------
extern "C" void kernel_launch(void* const* d_in, const int* in_sizes, int n_in,
                              void* d_out, int out_size)
{
    const float* query = (const float*)d_in[0];
    const float* key   = (const float*)d_in[1];
    const float* value = (const float*)d_in[2];
    const float* mask  = (const float*)d_in[3];
    const float* wq    = (const float*)d_in[4];
    const float* bq    = (const float*)d_in[5];
    const float* wk    = (const float*)d_in[6];
    const float* bk    = (const float*)d_in[7];
    const float* wv    = (const float*)d_in[8];
    const float* bv    = (const float*)d_in[9];
    const float* wo    = (const float*)d_in[10];
    const float* bo    = (const float*)d_in[11];
    float* out = (float*)d_out;

    cudaFuncSetAttribute(gemm_mma_kernel<0>, cudaFuncAttributeMaxDynamicSharedMemorySize, GEMM_SMEM);
    cudaFuncSetAttribute(gemm_mma_kernel<1>, cudaFuncAttributeMaxDynamicSharedMemorySize, GEMM_SMEM);
    cudaFuncSetAttribute(attn_mma_kernel,    cudaFuncAttributeMaxDynamicSharedMemorySize, ATT_SMEM);

    prep_kernel<<<8192, 256>>>(query, key, value, wq, wk, wv, wo, mask);

    dim3 gq(NDM/128, 4096/64, 3);           // (4, 64, 3)
    gemm_mma_kernel<0><<<gq, 128, GEMM_SMEM>>>(bq, bk, bv, nullptr);

    dim3 ga(NS/128, NB*NH);                 // (16, 16)
    attn_mma_kernel<<<ga, 128, ATT_SMEM>>>(mask);

    dim3 go(NDM/128, 4096/64);              // (4, 64)
    gemm_mma_kernel<1><<<go, 128, GEMM_SMEM>>>(bo, nullptr, nullptr, out);
}